// round 12
// baseline (speedup 1.0000x reference)
#include <cuda_runtime.h>
#include <cuda_fp16.h>
#include <cstdint>

#define THREADS 256
#define GRID 304          // 2 CTAs/SM x 152 SMs (GB300)
#define NTILES 2048       // 8 batches x 256 queries

// prep-built W1^T fp16 image (hi only), XOR-swizzled rows of 128B
__device__ __align__(16) uint8_t g_B1[32768];
// prep-built W2 mma B-frag image (hi only): u32[128 k2][8 n]
__device__ __align__(16) uint8_t g_W2[4096];

// smem byte offsets
#define A_OFF      0        // feat fp16 [256][72], stride 144
#define B1H_OFF    36864    // 32768 (swizzled 128B rows)
#define W2F_OFF    69632    // u32 [128][8]
#define B1V_OFF    73728    // 256 f32
#define B2V_OFF    74752    // 8 f32
#define SMEM_BYTES 74784

#define LDMX4(r, a) asm volatile( \
    "ldmatrix.sync.aligned.m8n8.x4.shared.b16 {%0,%1,%2,%3}, [%4];" \
    : "=r"((r)[0]), "=r"((r)[1]), "=r"((r)[2]), "=r"((r)[3]) : "r"(a))

static __device__ __forceinline__ uint32_t smem_u32(const void* p) {
    uint32_t a;
    asm("{ .reg .u64 t; cvta.to.shared.u64 t, %1; cvt.u32.u64 %0, t; }" : "=r"(a) : "l"(p));
    return a;
}
static __device__ __forceinline__ void mma16816(float* c, const uint32_t* a,
                                                uint32_t b0, uint32_t b1) {
    asm("mma.sync.aligned.m16n8k16.row.col.f32.f16.f16.f32 "
        "{%0,%1,%2,%3}, {%4,%5,%6,%7}, {%8,%9}, {%0,%1,%2,%3};"
        : "+f"(c[0]), "+f"(c[1]), "+f"(c[2]), "+f"(c[3])
        : "r"(a[0]), "r"(a[1]), "r"(a[2]), "r"(a[3]), "r"(b0), "r"(b1));
}
static __device__ __forceinline__ uint32_t packh2(float x, float y) {
    uint32_t r;
    asm("cvt.rn.f16x2.f32 %0, %1, %2;" : "=r"(r) : "f"(y), "f"(x));
    return r;
}
static __device__ __forceinline__ float tanh_ap(float x) {
    float t;
    asm("tanh.approx.f32 %0, %1;" : "=f"(t) : "f"(x));
    return t;
}
// silu via tanh.approx: x*sigmoid(x) = 0.5x + 0.5x*tanh(x/2)
static __device__ __forceinline__ float silu_f(float x) {
    float hx = 0.5f * x;
    return fmaf(hx, tanh_ap(hx), hx);
}
// fourier ladder: given s1=sin(v), c1=cos(v), fill sin/cos at 2^0..2^(nf-1)
static __device__ __forceinline__ void four4(float v, float* fs, float* fc) {
    float s, c;
    __sincosf(v, &s, &c);
    fs[0] = s; fc[0] = c;
    #pragma unroll
    for (int k = 1; k < 4; ++k) {
        float s2 = 2.0f * s * c;
        float c2 = fmaf(-2.0f * s, s, 1.0f);
        s = s2; c = c2;
        fs[k] = s; fc[k] = c;
    }
}

__global__ void prep_kernel(const float* __restrict__ W1, const float* __restrict__ W2) {
    int t0 = blockIdx.x * blockDim.x + threadIdx.x;
    int stride = gridDim.x * blockDim.x;
    for (int idx = t0; idx < 64 * 256; idx += stride) {
        int k = idx >> 8, n = idx & 255;          // W1 is (64,256): W1[k][n]
        __half h = __float2half_rn(W1[idx]);
        uint32_t off = (uint32_t)(n * 128 + (((k >> 3) ^ (n & 7)) << 4) + (k & 7) * 2);
        *(uint16_t*)(g_B1 + off) = *(uint16_t*)&h;
    }
    for (int idx = t0; idx < 1024; idx += stride) {
        int k2 = idx >> 3, n = idx & 7;           // W2 is (256,8)
        __half h0 = __float2half_rn(W2[(2 * k2) * 8 + n]);
        __half h1 = __float2half_rn(W2[(2 * k2 + 1) * 8 + n]);
        ((uint32_t*)g_W2)[idx] =
            (uint32_t)*(uint16_t*)&h0 | ((uint32_t)*(uint16_t*)&h1 << 16);
    }
}

__global__ void __launch_bounds__(THREADS, 2)
relfeat_mma(const float* __restrict__ Q, const float* __restrict__ K,
            const float* __restrict__ b1, const float* __restrict__ b2,
            float* __restrict__ out) {
    extern __shared__ char sm[];
    const uint32_t smb = smem_u32(sm);
    const int t = threadIdx.x;
    const int w = t >> 5, lane = t & 31;
    const int g = lane >> 2, tq = lane & 3;

    // ---- stage weights ONCE per persistent CTA ----
    {
        const uint4* s1 = (const uint4*)g_B1;
        uint4* d1 = (uint4*)(sm + B1H_OFF);
        for (int idx = t; idx < 2048; idx += THREADS) d1[idx] = s1[idx];
        const uint4* s2 = (const uint4*)g_W2;
        uint4* d2 = (uint4*)(sm + W2F_OFF);
        for (int idx = t; idx < 256; idx += THREADS) d2[idx] = s2[idx];
        ((float*)(sm + B1V_OFF))[t] = b1[t];
        if (t < 8) ((float*)(sm + B2V_OFF))[t] = b2[t];
    }

    const float* b1v = (const float*)(sm + B1V_OFF);
    const float* b2v = (const float*)(sm + B2V_OFF);
    const uint32_t* w2h = (const uint32_t*)(sm + W2F_OFF);

    for (int tile = blockIdx.x; tile < NTILES; tile += GRID) {
        const int i = tile & 255, b = tile >> 8;

        // ---- features: thread t computes full 64-vector for row j = t ----
        {
            const float* qr = Q + ((size_t)b * 256 + i) * 10;
            const float* kr = K + ((size_t)b * 256 + t) * 10;
            float qpx = qr[3], qpy = qr[4], qvx = qr[5], qvy = qr[6];
            float dpx = kr[3] - qpx, dpy = kr[4] - qpy;
            float dvx = kr[5] - qvx, dvy = kr[6] - qvy;
            float dist = sqrtf(dpx * dpx + dpy * dpy + 1e-6f);
            float inv_dist = __fdividef(1.0f, dist + 0.1f);
            float binv = __fdividef(1.0f, dist + 1e-6f);
            float bxn = dpx * binv, byn = dpy * binv;
            float ata = bxn * qr[7] + byn * qr[8];
            float aspect = bxn * kr[7] + byn * kr[8];
            float dot = dpx * dvx + dpy * dvy;
            float ss = dvx * dvx + dvy * dvy;
            float ttca = tanh_ap(fmaxf(__fdividef(-dot, ss + 1e-6f), 0.0f));
            float same = (qr[0] == kr[0]) ? 1.0f : 0.0f;
            float dspd = sqrtf(kr[5] * kr[5] + kr[6] * kr[6]) -
                         sqrtf(qvx * qvx + qvy * qvy);

            float f[64];
            const float in4[4] = { dist, inv_dist, ata, aspect };
            #pragma unroll
            for (int d = 0; d < 4; ++d)
                four4(in4[d], f + d * 8, f + d * 8 + 4);
            const float in2[8] = { dpx, dpy, dvx, dvy, ttca, dist, same, dspd };
            #pragma unroll
            for (int d = 0; d < 8; ++d) {
                float s1, c1;
                __sincosf(in2[d], &s1, &c1);
                float s2 = 2.0f * s1 * c1;
                float c2 = fmaf(-2.0f * s1, s1, 1.0f);
                f[32 + d * 4]     = s1; f[32 + d * 4 + 1] = s2;
                f[32 + d * 4 + 2] = c1; f[32 + d * 4 + 3] = c2;
            }
            #pragma unroll
            for (int q = 0; q < 8; ++q) {
                uint32_t h0 = packh2(f[8 * q],     f[8 * q + 1]);
                uint32_t h1 = packh2(f[8 * q + 2], f[8 * q + 3]);
                uint32_t h2 = packh2(f[8 * q + 4], f[8 * q + 5]);
                uint32_t h3 = packh2(f[8 * q + 6], f[8 * q + 7]);
                *(uint4*)(sm + A_OFF + (uint32_t)(t * 144 + q * 16)) =
                    make_uint4(h0, h1, h2, h3);
            }
        }
        __syncthreads();

        // ---- A fragments: warp w owns rows w*32..w*32+31 (2 m-tiles) ----
        uint32_t ah[2][4][4];
        #pragma unroll
        for (int mt = 0; mt < 2; ++mt)
            #pragma unroll
            for (int s = 0; s < 4; ++s) {
                uint32_t row = (uint32_t)(w * 32 + mt * 16 + (lane & 15));
                uint32_t addr = smb + A_OFF + row * 144 + 32 * s +
                                ((lane >> 4) & 1) * 16;
                LDMX4(ah[mt][s], addr);
            }
        __syncthreads();   // all frag loads done before next tile's A writes

        float o[2][4];
        #pragma unroll
        for (int mt = 0; mt < 2; ++mt) {
            o[mt][0] = b2v[2 * tq]; o[mt][1] = b2v[2 * tq + 1];
            o[mt][2] = o[mt][0];    o[mt][3] = o[mt][1];
        }

        #pragma unroll 2
        for (int cch = 0; cch < 4; ++cch) {
            #pragma unroll
            for (int half = 0; half < 2; ++half) {
                const int nbase = cch * 64 + half * 32;
                float acc[2][4][4];
                #pragma unroll
                for (int nt = 0; nt < 4; ++nt) {
                    const float2 bb = *(const float2*)(b1v + nbase + nt * 8 + 2 * tq);
                    #pragma unroll
                    for (int mt = 0; mt < 2; ++mt) {
                        acc[mt][nt][0] = bb.x; acc[mt][nt][1] = bb.y;
                        acc[mt][nt][2] = bb.x; acc[mt][nt][3] = bb.y;
                    }
                }
                #pragma unroll
                for (int s2m = 0; s2m < 2; ++s2m)
                    #pragma unroll
                    for (int nt = 0; nt < 4; ++nt) {
                        uint32_t brow = (uint32_t)(nbase + nt * 8 + (lane & 7));
                        uint32_t c16 = (uint32_t)(4 * s2m + (lane >> 3));
                        uint32_t baddr = smb + B1H_OFF + brow * 128 +
                                         ((c16 ^ (brow & 7)) << 4);
                        uint32_t bh[4];
                        LDMX4(bh, baddr);
                        const int s = 2 * s2m;
                        #pragma unroll
                        for (int mt = 0; mt < 2; ++mt) {
                            mma16816(acc[mt][nt], ah[mt][s],     bh[0], bh[1]);
                            mma16816(acc[mt][nt], ah[mt][s + 1], bh[2], bh[3]);
                        }
                    }
                // ---- silu + GEMM2 (W2 hi only) ----
                #pragma unroll
                for (int s2 = 0; s2 < 2; ++s2) {
                    const int s2g = half * 2 + s2;
                    const int kw = (cch * 32 + 8 * s2g + tq) * 8 + g;
                    const uint32_t b0h = w2h[kw], b1h = w2h[kw + 32];
                    #pragma unroll
                    for (int mt = 0; mt < 2; ++mt) {
                        uint32_t a2[4];
                        a2[0] = packh2(silu_f(acc[mt][2 * s2][0]),
                                       silu_f(acc[mt][2 * s2][1]));
                        a2[1] = packh2(silu_f(acc[mt][2 * s2][2]),
                                       silu_f(acc[mt][2 * s2][3]));
                        a2[2] = packh2(silu_f(acc[mt][2 * s2 + 1][0]),
                                       silu_f(acc[mt][2 * s2 + 1][1]));
                        a2[3] = packh2(silu_f(acc[mt][2 * s2 + 1][2]),
                                       silu_f(acc[mt][2 * s2 + 1][3]));
                        mma16816(o[mt], a2, b0h, b1h);
                    }
                }
            }
        }

        // ---- store out[b,h,i,j] ----
        #pragma unroll
        for (int mt = 0; mt < 2; ++mt) {
            const int j0 = w * 32 + mt * 16 + g;
            const size_t p0 = (((size_t)(b * 8 + 2 * tq)) * 256 + i) * 256 + j0;
            const size_t p1 = (((size_t)(b * 8 + 2 * tq + 1)) * 256 + i) * 256 + j0;
            out[p0]     = o[mt][0];
            out[p1]     = o[mt][1];
            out[p0 + 8] = o[mt][2];
            out[p1 + 8] = o[mt][3];
        }
    }
}

extern "C" void kernel_launch(void* const* d_in, const int* in_sizes, int n_in,
                              void* d_out, int out_size) {
    const float* Q  = (const float*)d_in[0];
    const float* K  = (const float*)d_in[1];
    const float* W1 = (const float*)d_in[2];
    const float* b1 = (const float*)d_in[3];
    const float* W2 = (const float*)d_in[4];
    const float* b2 = (const float*)d_in[5];
    float* out = (float*)d_out;

    prep_kernel<<<16, THREADS>>>(W1, W2);
    cudaFuncSetAttribute(relfeat_mma, cudaFuncAttributeMaxDynamicSharedMemorySize,
                         SMEM_BYTES);
    relfeat_mma<<<GRID, THREADS, SMEM_BYTES>>>(Q, K, b1, b2, out);
}